// round 1
// baseline (speedup 1.0000x reference)
#include <cuda_runtime.h>
#include <cstdint>

// Problem constants
#define NB 16        // batch elems per CTA
#define NTHREADS 128
#define HH 50
#define GG 200       // 4*H
#define TSTEPS 512
#define IIN 12
#define BTOT 2048

// Concatenated-input matvec dims:
// layer0: in = [x(12) | h0(50) | pad(2)] -> K0 = 64
// layer1: in = [h0'(50) pad(2) | h1(50) pad(2)] -> K1 = 104
#define K0 64
#define K1 104
// Padded SMEM row strides for weights (floats) chosen conflict-free for LDS.128:
// stride*lane mod 32 must tile all banks: 68 -> 4L mod 32, 108 -> 12L mod 32. Both OK.
#define K0S 68
#define K1S 108
#define RPAD 228     // rows padded: max row index = 100+31+96 = 227

// SMEM layout (floats)
#define W0_OFF 0
#define W1_OFF (RPAD*K0S)
#define IN0_OFF (W1_OFF + RPAD*K1S)
#define IN1_OFF (IN0_OFF + NB*K0)
#define GT_OFF  (IN1_OFF + NB*K1)
#define BS_OFF  (GT_OFF + NB*GG)
#define SMEM_FLOATS (BS_OFF + 2*GG)
#define SMEM_BYTES (SMEM_FLOATS*4)

__device__ __forceinline__ unsigned long long fma2(unsigned long long a,
                                                   unsigned long long b,
                                                   unsigned long long c) {
    unsigned long long d;
    asm("fma.rn.f32x2 %0, %1, %2, %3;" : "=l"(d) : "l"(a), "l"(b), "l"(c));
    return d;
}

__device__ __forceinline__ float sumhalves(unsigned long long v) {
    float lo = __uint_as_float((unsigned)(v & 0xffffffffull));
    float hi = __uint_as_float((unsigned)(v >> 32));
    return lo + hi;
}

__device__ __forceinline__ float fsigmoid(float x) {
    float e = __expf(-x);                    // x<<0 -> inf -> result 0 (correct)
    return __fdividef(1.0f, 1.0f + e);
}

__device__ __forceinline__ float ftanh(float x) {
    float a = fabsf(x);
    float e = __expf(2.0f * a);              // may be inf -> 2/(inf) = 0 -> r = 1 (correct)
    float r = 1.0f - __fdividef(2.0f, e + 1.0f);
    return copysignf(r, x);
}

// One concatenated matvec: gates[b][row] = bias[row] + sum_k W[row][k]*in[b][k]
// Warp layout: rbase = rg*100 + lane; rows rbase + {0,32,64,96}; batches oct*8..oct*8+7.
// KC = number of 4-float chunks actually used; WSTR/ISTR = row strides in ulonglong2 units.
template<int KC, int WSTR, int ISTR>
__device__ __forceinline__ void matvec(const float* Wm, const float* inp,
                                       float* gates, const float* bias,
                                       int rbase, int oct, int lane) {
    unsigned long long acc[4][8];
#pragma unroll
    for (int i = 0; i < 4; i++)
#pragma unroll
        for (int b = 0; b < 8; b++) acc[i][b] = 0ull;

    const ulonglong2* Wv = reinterpret_cast<const ulonglong2*>(Wm);
    const ulonglong2* Iv = reinterpret_cast<const ulonglong2*>(inp);

#pragma unroll 2
    for (int kc = 0; kc < KC; ++kc) {
        ulonglong2 w0 = Wv[(rbase      ) * WSTR + kc];
        ulonglong2 w1 = Wv[(rbase + 32 ) * WSTR + kc];
        ulonglong2 w2 = Wv[(rbase + 64 ) * WSTR + kc];
        ulonglong2 w3 = Wv[(rbase + 96 ) * WSTR + kc];
#pragma unroll
        for (int b = 0; b < 8; b++) {
            ulonglong2 v = Iv[(oct * 8 + b) * ISTR + kc];   // broadcast LDS.128
            acc[0][b] = fma2(w0.x, v.x, acc[0][b]);
            acc[0][b] = fma2(w0.y, v.y, acc[0][b]);
            acc[1][b] = fma2(w1.x, v.x, acc[1][b]);
            acc[1][b] = fma2(w1.y, v.y, acc[1][b]);
            acc[2][b] = fma2(w2.x, v.x, acc[2][b]);
            acc[2][b] = fma2(w2.y, v.y, acc[2][b]);
            acc[3][b] = fma2(w3.x, v.x, acc[3][b]);
            acc[3][b] = fma2(w3.y, v.y, acc[3][b]);
        }
    }
    // writeback valid rows (rr < 100 within this row-group)
#pragma unroll
    for (int i = 0; i < 4; i++) {
        int rr = lane + 32 * i;
        if (rr < 100) {
            int row = rbase + 32 * i;
            float bs = bias[row];
#pragma unroll
            for (int b = 0; b < 8; b++)
                gates[(oct * 8 + b) * GG + row] = sumhalves(acc[i][b]) + bs;
        }
    }
}

__global__ void __launch_bounds__(NTHREADS, 1)
lstm_kernel(const float* __restrict__ x,
            const float* __restrict__ w_ih0, const float* __restrict__ w_hh0,
            const float* __restrict__ b_ih0, const float* __restrict__ b_hh0,
            const float* __restrict__ w_ih1, const float* __restrict__ w_hh1,
            const float* __restrict__ b_ih1, const float* __restrict__ b_hh1,
            const float* __restrict__ w_out, const float* __restrict__ b_out,
            float* __restrict__ out) {
    extern __shared__ float smem[];
    float* W0    = smem + W0_OFF;   // [RPAD][K0S] zero-padded
    float* W1    = smem + W1_OFF;   // [RPAD][K1S]
    float* in0   = smem + IN0_OFF;  // [NB][K0]  : x | h0 | pad
    float* in1   = smem + IN1_OFF;  // [NB][K1]  : h0' pad | h1 pad
    float* gates = smem + GT_OFF;   // [NB][GG]
    float* bias  = smem + BS_OFF;   // [2][GG]

    const int tid = threadIdx.x;
    const int bbase = blockIdx.x * NB;

    // ---- one-time: stage weights/biases into SMEM (zero padded) ----
    for (int idx = tid; idx < RPAD * K0S; idx += NTHREADS) {
        int r = idx / K0S, k = idx % K0S;
        float v = 0.f;
        if (r < GG) {
            if (k < IIN)                 v = w_ih0[r * IIN + k];
            else if (k < IIN + HH)       v = w_hh0[r * HH + (k - IIN)];
        }
        W0[idx] = v;
    }
    for (int idx = tid; idx < RPAD * K1S; idx += NTHREADS) {
        int r = idx / K1S, k = idx % K1S;
        float v = 0.f;
        if (r < GG) {
            if (k < HH)                       v = w_ih1[r * HH + k];
            else if (k >= 52 && k < 52 + HH)  v = w_hh1[r * HH + (k - 52)];
        }
        W1[idx] = v;
    }
    for (int idx = tid; idx < GG; idx += NTHREADS) {
        bias[idx]      = b_ih0[idx] + b_hh0[idx];
        bias[GG + idx] = b_ih1[idx] + b_hh1[idx];
    }
    for (int idx = tid; idx < NB * K0; idx += NTHREADS) in0[idx] = 0.f;
    for (int idx = tid; idx < NB * K1; idx += NTHREADS) in1[idx] = 0.f;
    __syncthreads();

    // stage x[t=0]
    if (tid < 96) {
        int b = tid / 6, p = tid % 6;
        float2 v = *reinterpret_cast<const float2*>(x + ((size_t)(bbase + b) * TSTEPS + 0) * IIN + 2 * p);
        *reinterpret_cast<float2*>(in0 + b * K0 + 2 * p) = v;
    }
    __syncthreads();

    const int warp = tid >> 5, lane = tid & 31;
    const int rg  = warp & 1;        // row group: rows [rg*100, rg*100+100)
    const int oct = warp >> 1;       // batch octet
    const int rbase = rg * 100 + lane;

    // update-phase mapping: thread -> (batch ub, j = uj + 8m)
    const int ub = tid >> 3;
    const int uj = tid & 7;
    float c0r[7], c1r[7];
#pragma unroll
    for (int m = 0; m < 7; m++) { c0r[m] = 0.f; c1r[m] = 0.f; }

    for (int t = 0; t < TSTEPS; ++t) {
        // prefetch x[t+1] into regs (hidden behind phase A compute)
        float2 xpre = make_float2(0.f, 0.f);
        {
            int tn = (t + 1 < TSTEPS) ? (t + 1) : (TSTEPS - 1);
            if (tid < 96) {
                int b = tid / 6, p = tid % 6;
                xpre = *reinterpret_cast<const float2*>(x + ((size_t)(bbase + b) * TSTEPS + tn) * IIN + 2 * p);
            }
        }

        // ---- Phase A: layer0 gates = [W_ih0|W_hh0] . [x|h0] + bias0 ----
        matvec<K0 / 4, K0S / 4, K0 / 4>(W0, in0, gates, bias, rbase, oct, lane);
        __syncthreads();

        // ---- Phase B: layer0 elementwise update ----
#pragma unroll
        for (int m = 0; m < 7; m++) {
            int j = uj + 8 * m;
            if (j < HH) {
                float gi = gates[ub * GG + j];
                float gf = gates[ub * GG + 50 + j];
                float gg = gates[ub * GG + 100 + j];
                float go = gates[ub * GG + 150 + j];
                float i_ = fsigmoid(gi), f_ = fsigmoid(gf);
                float g_ = ftanh(gg),   o_ = fsigmoid(go);
                float c = f_ * c0r[m] + i_ * g_;
                c0r[m] = c;
                float h = o_ * ftanh(c);
                in0[ub * K0 + IIN + j] = h;   // feeds layer0 recurrence (t+1)
                in1[ub * K1 + j]       = h;   // feeds layer1 input proj (t)
            }
        }
        // store prefetched x[t+1] (phase A already consumed x[t])
        if (tid < 96) {
            int b = tid / 6, p = tid % 6;
            *reinterpret_cast<float2*>(in0 + b * K0 + 2 * p) = xpre;
        }
        __syncthreads();

        // ---- Phase C: layer1 gates = [W_ih1|W_hh1] . [h0'|h1] + bias1 ----
        matvec<K1 / 4, K1S / 4, K1 / 4>(W1, in1, gates, bias + GG, rbase, oct, lane);
        __syncthreads();

        // ---- Phase D: layer1 elementwise update ----
#pragma unroll
        for (int m = 0; m < 7; m++) {
            int j = uj + 8 * m;
            if (j < HH) {
                float gi = gates[ub * GG + j];
                float gf = gates[ub * GG + 50 + j];
                float gg = gates[ub * GG + 100 + j];
                float go = gates[ub * GG + 150 + j];
                float i_ = fsigmoid(gi), f_ = fsigmoid(gf);
                float g_ = ftanh(gg),   o_ = fsigmoid(go);
                float c = f_ * c1r[m] + i_ * g_;
                c1r[m] = c;
                float h = o_ * ftanh(c);
                in1[ub * K1 + 52 + j] = h;    // feeds layer1 recurrence (t+1)
            }
        }
        __syncthreads();
    }

    // ---- head: out[b] = sigmoid(w_out . h1_last + b_out) ----
    if (tid < NB) {
        float acc = b_out[0];
#pragma unroll
        for (int j = 0; j < HH; j++)
            acc += w_out[j] * in1[tid * K1 + 52 + j];
        out[bbase + tid] = fsigmoid(acc);
    }
}

extern "C" void kernel_launch(void* const* d_in, const int* in_sizes, int n_in,
                              void* d_out, int out_size) {
    const float* x     = (const float*)d_in[0];
    const float* w_ih0 = (const float*)d_in[1];
    const float* w_hh0 = (const float*)d_in[2];
    const float* b_ih0 = (const float*)d_in[3];
    const float* b_hh0 = (const float*)d_in[4];
    const float* w_ih1 = (const float*)d_in[5];
    const float* w_hh1 = (const float*)d_in[6];
    const float* b_ih1 = (const float*)d_in[7];
    const float* b_hh1 = (const float*)d_in[8];
    const float* w_out = (const float*)d_in[9];
    const float* b_out = (const float*)d_in[10];
    float* out = (float*)d_out;

    cudaFuncSetAttribute(lstm_kernel, cudaFuncAttributeMaxDynamicSharedMemorySize, SMEM_BYTES);
    lstm_kernel<<<BTOT / NB, NTHREADS, SMEM_BYTES>>>(
        x, w_ih0, w_hh0, b_ih0, b_hh0, w_ih1, w_hh1, b_ih1, b_hh1, w_out, b_out, out);
}

// round 3
// speedup vs baseline: 1.3216x; 1.3216x over previous
#include <cuda_runtime.h>
#include <cstdint>

// Problem constants
#define NB 16        // batch elems per CTA
#define NTHREADS 512
#define HH 50
#define GG 200       // 4*H
#define TSTEPS 512
#define IIN 12
#define BTOT 2048

// Concatenated-input matvec dims:
// layer0: in = [x(12) | h0(50) | pad(2)] -> K0 = 64
// layer1: in = [h0'(50) pad(2) | h1(50) pad(2)] -> K1 = 104
#define K0 64
#define K1 104
// Padded SMEM row strides (floats): 68 = 4 mod 32, 108 = 12 mod 32.
// For LDS.128 (8-lane phases, 4 banks/lane) both tile all 32 banks -> conflict-free.
#define K0S 68
#define K1S 108
#define RPAD 228     // rows padded: max row index = 100+31+96 = 227

// SMEM layout (floats)
#define W0_OFF 0
#define W1_OFF (RPAD*K0S)
#define IN0_OFF (W1_OFF + RPAD*K1S)
#define IN1_OFF (IN0_OFF + NB*K0)
#define GT_OFF  (IN1_OFF + NB*K1)
#define BS_OFF  (GT_OFF + NB*GG)
#define SMEM_FLOATS (BS_OFF + 2*GG)
#define SMEM_BYTES (SMEM_FLOATS*4)

__device__ __forceinline__ unsigned long long fma2(unsigned long long a,
                                                   unsigned long long b,
                                                   unsigned long long c) {
    unsigned long long d;
    asm("fma.rn.f32x2 %0, %1, %2, %3;" : "=l"(d) : "l"(a), "l"(b), "l"(c));
    return d;
}

__device__ __forceinline__ float sumhalves(unsigned long long v) {
    float lo = __uint_as_float((unsigned)(v & 0xffffffffull));
    float hi = __uint_as_float((unsigned)(v >> 32));
    return lo + hi;
}

__device__ __forceinline__ float fsigmoid(float x) {
    float e = __expf(-x);                    // x<<0 -> inf -> result 0 (correct)
    return __fdividef(1.0f, 1.0f + e);
}

__device__ __forceinline__ float ftanh(float x) {
    float a = fabsf(x);
    float e = __expf(2.0f * a);              // may be inf -> 2/(inf+1)=0 -> r=1 (correct)
    float r = 1.0f - __fdividef(2.0f, e + 1.0f);
    return copysignf(r, x);
}

// Concatenated matvec: gates[b][row] = bias[row] + sum_k W[row][k]*in[b][k]
// Warp layout: rows rbase + {0,32,64,96} (rbase = rg*100 + lane); batches {bb, bb+1}.
template<int KC, int WSTR, int ISTR>
__device__ __forceinline__ void matvec(const float* Wm, const float* inp,
                                       float* gates, const float* bias,
                                       int rbase, int bb, int lane) {
    unsigned long long acc[4][2];
#pragma unroll
    for (int i = 0; i < 4; i++)
#pragma unroll
        for (int b = 0; b < 2; b++) acc[i][b] = 0ull;

    const ulonglong2* Wv = reinterpret_cast<const ulonglong2*>(Wm);
    const ulonglong2* Iv = reinterpret_cast<const ulonglong2*>(inp);

#pragma unroll 4
    for (int kc = 0; kc < KC; ++kc) {
        ulonglong2 w0 = Wv[(rbase      ) * WSTR + kc];
        ulonglong2 w1 = Wv[(rbase + 32 ) * WSTR + kc];
        ulonglong2 w2 = Wv[(rbase + 64 ) * WSTR + kc];
        ulonglong2 w3 = Wv[(rbase + 96 ) * WSTR + kc];
#pragma unroll
        for (int b = 0; b < 2; b++) {
            ulonglong2 v = Iv[(bb + b) * ISTR + kc];   // broadcast LDS.128
            acc[0][b] = fma2(w0.x, v.x, acc[0][b]);
            acc[0][b] = fma2(w0.y, v.y, acc[0][b]);
            acc[1][b] = fma2(w1.x, v.x, acc[1][b]);
            acc[1][b] = fma2(w1.y, v.y, acc[1][b]);
            acc[2][b] = fma2(w2.x, v.x, acc[2][b]);
            acc[2][b] = fma2(w2.y, v.y, acc[2][b]);
            acc[3][b] = fma2(w3.x, v.x, acc[3][b]);
            acc[3][b] = fma2(w3.y, v.y, acc[3][b]);
        }
    }
#pragma unroll
    for (int i = 0; i < 4; i++) {
        int rr = lane + 32 * i;
        if (rr < 100) {
            int row = rbase + 32 * i;
            float bs = bias[row];
#pragma unroll
            for (int b = 0; b < 2; b++)
                gates[(bb + b) * GG + row] = sumhalves(acc[i][b]) + bs;
        }
    }
}

__global__ void __launch_bounds__(NTHREADS, 1)
lstm_kernel(const float* __restrict__ x,
            const float* __restrict__ w_ih0, const float* __restrict__ w_hh0,
            const float* __restrict__ b_ih0, const float* __restrict__ b_hh0,
            const float* __restrict__ w_ih1, const float* __restrict__ w_hh1,
            const float* __restrict__ b_ih1, const float* __restrict__ b_hh1,
            const float* __restrict__ w_out, const float* __restrict__ b_out,
            float* __restrict__ out) {
    extern __shared__ float smem[];
    float* W0    = smem + W0_OFF;   // [RPAD][K0S] zero-padded
    float* W1    = smem + W1_OFF;   // [RPAD][K1S]
    float* in0   = smem + IN0_OFF;  // [NB][K0]  : x | h0 | pad
    float* in1   = smem + IN1_OFF;  // [NB][K1]  : h0' pad | h1 pad
    float* gates = smem + GT_OFF;   // [NB][GG]
    float* bias  = smem + BS_OFF;   // [2][GG]

    const int tid = threadIdx.x;
    const int bbase = blockIdx.x * NB;

    // ---- one-time: stage weights/biases into SMEM (zero padded) ----
    for (int idx = tid; idx < RPAD * K0S; idx += NTHREADS) {
        int r = idx / K0S, k = idx % K0S;
        float v = 0.f;
        if (r < GG) {
            if (k < IIN)                 v = w_ih0[r * IIN + k];
            else if (k < IIN + HH)       v = w_hh0[r * HH + (k - IIN)];
        }
        W0[idx] = v;
    }
    for (int idx = tid; idx < RPAD * K1S; idx += NTHREADS) {
        int r = idx / K1S, k = idx % K1S;
        float v = 0.f;
        if (r < GG) {
            if (k < HH)                       v = w_ih1[r * HH + k];
            else if (k >= 52 && k < 52 + HH)  v = w_hh1[r * HH + (k - 52)];
        }
        W1[idx] = v;
    }
    for (int idx = tid; idx < GG; idx += NTHREADS) {
        bias[idx]      = b_ih0[idx] + b_hh0[idx];
        bias[GG + idx] = b_ih1[idx] + b_hh1[idx];
    }
    for (int idx = tid; idx < NB * K0; idx += NTHREADS) in0[idx] = 0.f;
    for (int idx = tid; idx < NB * K1; idx += NTHREADS) in1[idx] = 0.f;
    __syncthreads();

    // stage x[t=0]
    if (tid < 96) {
        int b = tid / 6, p = tid % 6;
        float2 v = *reinterpret_cast<const float2*>(x + ((size_t)(bbase + b) * TSTEPS + 0) * IIN + 2 * p);
        *reinterpret_cast<float2*>(in0 + b * K0 + 2 * p) = v;
    }
    __syncthreads();

    const int warp = tid >> 5, lane = tid & 31;
    const int rg = warp & 1;          // row group: rows [rg*100, rg*100+100)
    const int bb = (warp >> 1) * 2;   // batch pair start
    const int rbase = rg * 100 + lane;

    // update-phase mapping: thread -> (batch ub, hidden units j0, j0+32)
    const int ub = tid & 15;
    const int j0 = tid >> 4;          // 0..31
    float c0r[2], c1r[2];
    c0r[0] = c0r[1] = c1r[0] = c1r[1] = 0.f;

    for (int t = 0; t < TSTEPS; ++t) {
        // prefetch x[t+1] into regs (hidden behind phase A compute)
        float2 xpre = make_float2(0.f, 0.f);
        {
            int tn = (t + 1 < TSTEPS) ? (t + 1) : (TSTEPS - 1);
            if (tid < 96) {
                int b = tid / 6, p = tid % 6;
                xpre = *reinterpret_cast<const float2*>(x + ((size_t)(bbase + b) * TSTEPS + tn) * IIN + 2 * p);
            }
        }

        // ---- Phase A: layer0 gates = [W_ih0|W_hh0] . [x|h0] + bias0 ----
        matvec<K0 / 4, K0S / 4, K0 / 4>(W0, in0, gates, bias, rbase, bb, lane);
        __syncthreads();

        // ---- Phase B: layer0 elementwise update ----
#pragma unroll
        for (int m = 0; m < 2; m++) {
            int j = j0 + 32 * m;
            if (j < HH) {
                float gi = gates[ub * GG + j];
                float gf = gates[ub * GG + 50 + j];
                float gg = gates[ub * GG + 100 + j];
                float go = gates[ub * GG + 150 + j];
                float i_ = fsigmoid(gi), f_ = fsigmoid(gf);
                float g_ = ftanh(gg),   o_ = fsigmoid(go);
                float c = f_ * c0r[m] + i_ * g_;
                c0r[m] = c;
                float h = o_ * ftanh(c);
                in0[ub * K0 + IIN + j] = h;   // feeds layer0 recurrence (t+1)
                in1[ub * K1 + j]       = h;   // feeds layer1 input proj (t)
            }
        }
        // store prefetched x[t+1] (phase A already consumed x[t])
        if (tid < 96) {
            int b = tid / 6, p = tid % 6;
            *reinterpret_cast<float2*>(in0 + b * K0 + 2 * p) = xpre;
        }
        __syncthreads();

        // ---- Phase C: layer1 gates = [W_ih1|W_hh1] . [h0'|h1] + bias1 ----
        matvec<K1 / 4, K1S / 4, K1 / 4>(W1, in1, gates, bias + GG, rbase, bb, lane);
        __syncthreads();

        // ---- Phase D: layer1 elementwise update ----
#pragma unroll
        for (int m = 0; m < 2; m++) {
            int j = j0 + 32 * m;
            if (j < HH) {
                float gi = gates[ub * GG + j];
                float gf = gates[ub * GG + 50 + j];
                float gg = gates[ub * GG + 100 + j];
                float go = gates[ub * GG + 150 + j];
                float i_ = fsigmoid(gi), f_ = fsigmoid(gf);
                float g_ = ftanh(gg),   o_ = fsigmoid(go);
                float c = f_ * c1r[m] + i_ * g_;
                c1r[m] = c;
                float h = o_ * ftanh(c);
                in1[ub * K1 + 52 + j] = h;    // feeds layer1 recurrence (t+1)
            }
        }
        __syncthreads();
    }

    // ---- head: out[b] = sigmoid(w_out . h1_last + b_out) ----
    if (tid < NB) {
        float acc = b_out[0];
#pragma unroll
        for (int j = 0; j < HH; j++)
            acc += w_out[j] * in1[tid * K1 + 52 + j];
        out[bbase + tid] = fsigmoid(acc);
    }
}

extern "C" void kernel_launch(void* const* d_in, const int* in_sizes, int n_in,
                              void* d_out, int out_size) {
    const float* x     = (const float*)d_in[0];
    const float* w_ih0 = (const float*)d_in[1];
    const float* w_hh0 = (const float*)d_in[2];
    const float* b_ih0 = (const float*)d_in[3];
    const float* b_hh0 = (const float*)d_in[4];
    const float* w_ih1 = (const float*)d_in[5];
    const float* w_hh1 = (const float*)d_in[6];
    const float* b_ih1 = (const float*)d_in[7];
    const float* b_hh1 = (const float*)d_in[8];
    const float* w_out = (const float*)d_in[9];
    const float* b_out = (const float*)d_in[10];
    float* out = (float*)d_out;

    cudaFuncSetAttribute(lstm_kernel, cudaFuncAttributeMaxDynamicSharedMemorySize, SMEM_BYTES);
    lstm_kernel<<<BTOT / NB, NTHREADS, SMEM_BYTES>>>(
        x, w_ih0, w_hh0, b_ih0, b_hh0, w_ih1, w_hh1, b_ih1, b_hh1, w_out, b_out, out);
}

// round 4
// speedup vs baseline: 2.0271x; 1.5338x over previous
#include <cuda_runtime.h>
#include <cstdint>

#define NB 16
#define NTH 640
#define G0N 224          // warps 0..6  : layer0 group (200 active)
#define G1N 416          // warps 7..19 : layer1 group (400 active)
#define HH 50
#define GG 200
#define TSTEPS 512
#define IIN 12
#define BTOT 2048

#define K0 64            // layer0 concat input, padded: [x(12)|h0(50)|pad2]
#define K1 112           // layer1 concat input, padded: [h0(50)|pad6|h1(50)|pad6]
#define GP 20            // gate-partial row padding (floats)

// smem float offsets
#define IN0_OFF 0
#define IN1_OFF (IN0_OFF + NB*K0)        // double buffered [2][NB][K1]
#define B0_OFF  (IN1_OFF + 2*NB*K1)
#define B1_OFF  (B0_OFF + GG)
#define G0P_OFF (B1_OFF + GG)            // [2][GG][GP]
#define G1P_OFF (G0P_OFF + 2*GG*GP)      // [4][GG][GP]
#define SMEM_FLOATS (G1P_OFF + 4*GG*GP)
#define SMEM_BYTES (SMEM_FLOATS*4)

#define BARRIER(id,n) asm volatile("bar.sync %0, %1;" :: "r"(id), "r"(n) : "memory")

typedef unsigned long long ull;

__device__ __forceinline__ ull fma2(ull a, ull b, ull c) {
    ull d;
    asm("fma.rn.f32x2 %0, %1, %2, %3;" : "=l"(d) : "l"(a), "l"(b), "l"(c));
    return d;
}
__device__ __forceinline__ float sumh(ull v) {
    float lo = __uint_as_float((unsigned)(v & 0xffffffffull));
    float hi = __uint_as_float((unsigned)(v >> 32));
    return lo + hi;
}
__device__ __forceinline__ ull pk(float a, float b) {
    return (ull)__float_as_uint(a) | ((ull)__float_as_uint(b) << 32);
}
__device__ __forceinline__ float fsigmoid(float x) {
    float e = __expf(-x);
    return __fdividef(1.0f, 1.0f + e);
}
__device__ __forceinline__ float ftanh(float x) {
    float a = fabsf(x);
    float e = __expf(2.0f * a);
    float r = 1.0f - __fdividef(2.0f, e + 1.0f);
    return copysignf(r, x);
}
// weight gather for layer0 concat k: [x(12)|h0(50)|pad2]
__device__ __forceinline__ float wl0(const float* wi, const float* wh, int r, int f) {
    if (f < IIN) return wi[r * IIN + f];
    if (f < IIN + HH) return wh[r * HH + (f - IIN)];
    return 0.f;
}
// layer1 concat k: [h0(50)|pad6|h1(50)|pad6]
__device__ __forceinline__ float wl1(const float* wi, const float* wh, int r, int f) {
    if (f < HH) return wi[r * HH + f];
    if (f >= 56 && f < 56 + HH) return wh[r * HH + (f - 56)];
    return 0.f;
}

__global__ void __launch_bounds__(NTH, 1)
lstm_kernel(const float* __restrict__ x,
            const float* __restrict__ w_ih0, const float* __restrict__ w_hh0,
            const float* __restrict__ b_ih0, const float* __restrict__ b_hh0,
            const float* __restrict__ w_ih1, const float* __restrict__ w_hh1,
            const float* __restrict__ b_ih1, const float* __restrict__ b_hh1,
            const float* __restrict__ w_out, const float* __restrict__ b_out,
            float* __restrict__ out) {
    extern __shared__ float smem[];
    float* in0   = smem + IN0_OFF;   // [NB][K0]
    float* in1   = smem + IN1_OFF;   // [2][NB][K1]
    float* bias0 = smem + B0_OFF;
    float* bias1 = smem + B1_OFF;
    float* g0p   = smem + G0P_OFF;   // [2][GG][GP]
    float* g1p   = smem + G1P_OFF;   // [4][GG][GP]

    const int tid = threadIdx.x;
    const int bbase = blockIdx.x * NB;

    for (int i = tid; i < NB * K0; i += NTH)     in0[i] = 0.f;
    for (int i = tid; i < 2 * NB * K1; i += NTH) in1[i] = 0.f;
    for (int i = tid; i < GG; i += NTH) {
        bias0[i] = b_ih0[i] + b_hh0[i];
        bias1[i] = b_ih1[i] + b_hh1[i];
    }
    __syncthreads();
    if (tid < 96) {   // stage x(0)
        int b = tid / 6, p = tid % 6;
        *reinterpret_cast<float2*>(&in0[b * K0 + 2 * p]) =
            *reinterpret_cast<const float2*>(&x[((size_t)(bbase + b) * TSTEPS) * IIN + 2 * p]);
    }
    __syncthreads();

    if (tid < G0N) {
        // ================= LAYER-0 GROUP =================
        const bool act = tid < 200;
        const int rp = tid % 100, kh = tid / 100;   // (row-pair, k-half)
        const int r0 = 2 * rp, r1 = r0 + 1;
        ull wa[16], wb[16];
        if (act) {
#pragma unroll
            for (int i = 0; i < 16; i++) {
                int f = kh * 32 + 2 * i;
                wa[i] = pk(wl0(w_ih0, w_hh0, r0, f), wl0(w_ih0, w_hh0, r0, f + 1));
                wb[i] = pk(wl0(w_ih0, w_hh0, r1, f), wl0(w_ih0, w_hh0, r1, f + 1));
            }
        }
        const float bA = (act && kh == 0) ? bias0[r0] : 0.f;
        const float bB = (act && kh == 0) ? bias0[r1] : 0.f;
        const float* inbase = in0 + kh * 32;
        float* gout0 = g0p + (kh * GG + r0) * GP;
        float* gout1 = g0p + (kh * GG + r1) * GP;
        float c0s[4] = {0.f, 0.f, 0.f, 0.f};
        const int xb = tid / 6, xp = tid % 6;

        for (int s = 0; s <= TSTEPS; s++) {
            float2 xpre;
            if (s < TSTEPS) {
                if (tid < 96) {
                    int tn = (s + 1 < TSTEPS) ? s + 1 : TSTEPS - 1;
                    xpre = *reinterpret_cast<const float2*>(
                        &x[((size_t)(bbase + xb) * TSTEPS + tn) * IIN + 2 * xp]);
                }
                if (act) {
#pragma unroll
                    for (int wv = 0; wv < 4; wv++) {
                        ull a0[4] = {0, 0, 0, 0}, a1[4] = {0, 0, 0, 0};
#pragma unroll
                        for (int i = 0; i < 8; i++) {
#pragma unroll
                            for (int b = 0; b < 4; b++) {
                                ulonglong2 v = *reinterpret_cast<const ulonglong2*>(
                                    &inbase[(wv * 4 + b) * K0 + i * 4]);
                                a0[b] = fma2(wa[2 * i],     v.x, a0[b]);
                                a0[b] = fma2(wa[2 * i + 1], v.y, a0[b]);
                                a1[b] = fma2(wb[2 * i],     v.x, a1[b]);
                                a1[b] = fma2(wb[2 * i + 1], v.y, a1[b]);
                            }
                        }
                        float4 s0, s1;
                        s0.x = sumh(a0[0]) + bA; s0.y = sumh(a0[1]) + bA;
                        s0.z = sumh(a0[2]) + bA; s0.w = sumh(a0[3]) + bA;
                        s1.x = sumh(a1[0]) + bB; s1.y = sumh(a1[1]) + bB;
                        s1.z = sumh(a1[2]) + bB; s1.w = sumh(a1[3]) + bB;
                        *reinterpret_cast<float4*>(&gout0[wv * 4]) = s0;
                        *reinterpret_cast<float4*>(&gout1[wv * 4]) = s1;
                    }
                }
            }
            BARRIER(1, G0N);
            if (s < TSTEPS) {
                float* sb = in1 + (s & 1) * NB * K1;
#pragma unroll
                for (int k = 0; k < 4; k++) {
                    int c = tid + 224 * k;
                    if (c < 800) {
                        int j = c >> 4, b = c & 15;
                        float gi = g0p[(0 * GG + j) * GP + b]       + g0p[(1 * GG + j) * GP + b];
                        float gf = g0p[(0 * GG + 50 + j) * GP + b]  + g0p[(1 * GG + 50 + j) * GP + b];
                        float gg = g0p[(0 * GG + 100 + j) * GP + b] + g0p[(1 * GG + 100 + j) * GP + b];
                        float go = g0p[(0 * GG + 150 + j) * GP + b] + g0p[(1 * GG + 150 + j) * GP + b];
                        float i_ = fsigmoid(gi), f_ = fsigmoid(gf);
                        float g_ = ftanh(gg),   o_ = fsigmoid(go);
                        float cc = f_ * c0s[k] + i_ * g_;
                        c0s[k] = cc;
                        float h = o_ * ftanh(cc);
                        in0[b * K0 + IIN + j] = h;   // layer0 recurrence (t+1)
                        sb[b * K1 + j] = h;          // layer1 input (t)
                    }
                }
                if (tid < 96)
                    *reinterpret_cast<float2*>(&in0[xb * K0 + 2 * xp]) = xpre;
            }
            BARRIER(3, NTH);
        }
    } else {
        // ================= LAYER-1 GROUP =================
        const int t1 = tid - G0N;
        const bool act = t1 < 400;
        const int rp = t1 % 100, kq = t1 / 100;     // (row-pair, k-quarter)
        const int r0 = 2 * rp, r1 = r0 + 1;
        ull wa[14], wb[14];
        if (act) {
#pragma unroll
            for (int i = 0; i < 14; i++) {
                int f = kq * 28 + 2 * i;
                wa[i] = pk(wl1(w_ih1, w_hh1, r0, f), wl1(w_ih1, w_hh1, r0, f + 1));
                wb[i] = pk(wl1(w_ih1, w_hh1, r1, f), wl1(w_ih1, w_hh1, r1, f + 1));
            }
        }
        const float bA = (act && kq == 0) ? bias1[r0] : 0.f;
        const float bB = (act && kq == 0) ? bias1[r1] : 0.f;
        float* gout0 = g1p + (kq * GG + r0) * GP;
        float* gout1 = g1p + (kq * GG + r1) * GP;
        float c1s[2] = {0.f, 0.f};

        for (int s = 0; s <= TSTEPS; s++) {
            if (s >= 1 && act) {
                const float* ib = in1 + ((s - 1) & 1) * NB * K1 + kq * 28;
#pragma unroll
                for (int wv = 0; wv < 4; wv++) {
                    ull a0[4] = {0, 0, 0, 0}, a1[4] = {0, 0, 0, 0};
#pragma unroll
                    for (int i = 0; i < 7; i++) {
#pragma unroll
                        for (int b = 0; b < 4; b++) {
                            ulonglong2 v = *reinterpret_cast<const ulonglong2*>(
                                &ib[(wv * 4 + b) * K1 + i * 4]);
                            a0[b] = fma2(wa[2 * i],     v.x, a0[b]);
                            a0[b] = fma2(wa[2 * i + 1], v.y, a0[b]);
                            a1[b] = fma2(wb[2 * i],     v.x, a1[b]);
                            a1[b] = fma2(wb[2 * i + 1], v.y, a1[b]);
                        }
                    }
                    float4 s0, s1;
                    s0.x = sumh(a0[0]) + bA; s0.y = sumh(a0[1]) + bA;
                    s0.z = sumh(a0[2]) + bA; s0.w = sumh(a0[3]) + bA;
                    s1.x = sumh(a1[0]) + bB; s1.y = sumh(a1[1]) + bB;
                    s1.z = sumh(a1[2]) + bB; s1.w = sumh(a1[3]) + bB;
                    *reinterpret_cast<float4*>(&gout0[wv * 4]) = s0;
                    *reinterpret_cast<float4*>(&gout1[wv * 4]) = s1;
                }
            }
            BARRIER(2, G1N);
            if (s >= 1) {
                float* sb = in1 + (s & 1) * NB * K1;
#pragma unroll
                for (int k = 0; k < 2; k++) {
                    int c = t1 + 416 * k;
                    if (c < 800) {
                        int j = c >> 4, b = c & 15;
                        float gi = 0.f, gf = 0.f, gg = 0.f, go = 0.f;
#pragma unroll
                        for (int p = 0; p < 4; p++) {
                            gi += g1p[(p * GG + j) * GP + b];
                            gf += g1p[(p * GG + 50 + j) * GP + b];
                            gg += g1p[(p * GG + 100 + j) * GP + b];
                            go += g1p[(p * GG + 150 + j) * GP + b];
                        }
                        float i_ = fsigmoid(gi), f_ = fsigmoid(gf);
                        float g_ = ftanh(gg),   o_ = fsigmoid(go);
                        float cc = f_ * c1s[k] + i_ * g_;
                        c1s[k] = cc;
                        float h = o_ * ftanh(cc);
                        sb[b * K1 + 56 + j] = h;     // layer1 recurrence
                    }
                }
            }
            BARRIER(3, NTH);
        }
    }
    __syncthreads();

    // head: final h1 = h1(511), written at superstep 512 into buffer (512&1)=0
    if (tid < NB) {
        float acc = b_out[0];
        const float* hb = in1 + 0 * NB * K1 + tid * K1 + 56;
#pragma unroll
        for (int j = 0; j < HH; j++) acc += w_out[j] * hb[j];
        out[bbase + tid] = fsigmoid(acc);
    }
}

extern "C" void kernel_launch(void* const* d_in, const int* in_sizes, int n_in,
                              void* d_out, int out_size) {
    const float* x     = (const float*)d_in[0];
    const float* w_ih0 = (const float*)d_in[1];
    const float* w_hh0 = (const float*)d_in[2];
    const float* b_ih0 = (const float*)d_in[3];
    const float* b_hh0 = (const float*)d_in[4];
    const float* w_ih1 = (const float*)d_in[5];
    const float* w_hh1 = (const float*)d_in[6];
    const float* b_ih1 = (const float*)d_in[7];
    const float* b_hh1 = (const float*)d_in[8];
    const float* w_out = (const float*)d_in[9];
    const float* b_out = (const float*)d_in[10];
    float* out = (float*)d_out;

    cudaFuncSetAttribute(lstm_kernel, cudaFuncAttributeMaxDynamicSharedMemorySize, SMEM_BYTES);
    lstm_kernel<<<BTOT / NB, NTH, SMEM_BYTES>>>(
        x, w_ih0, w_hh0, b_ih0, b_hh0, w_ih1, w_hh1, b_ih1, b_hh1, w_out, b_out, out);
}